// round 3
// baseline (speedup 1.0000x reference)
#include <cuda_runtime.h>
#include <cuda_bf16.h>
#include <cstdint>
#include <cstddef>

// ---------------- problem constants ----------------
#define B_SZ   256
#define T_SZ   1024
#define I_SZ   128
#define H_SZ   256
#define KDIM   (H_SZ + I_SZ)     // 384
#define CLC    8                 // CTAs per cluster (hidden split)
#define NB     16                // batch rows per cluster
#define NGRP   (B_SZ / NB)       // 16 clusters
#define GRID_CTAS (NGRP * CLC)   // 128 CTAs
#define THREADS 256              // 8 warps -> 2 per SMSP

// SMEM layout (floats)
#define B_STRIDE 388                       // padded row stride for Bs [16][388]
#define A_ELEMS  (KDIM * 128)              // A_T[k][r], k-major, 49152 floats
#define B_ELEMS  (NB * B_STRIDE)           // 6208 floats
#define SMEM_FLOATS (A_ELEMS + B_ELEMS)
#define SMEM_BYTES  (SMEM_FLOATS * 4)      // 221440 bytes

// ping-pong short-state exchange buffer (L2)
__device__ float g_shortbuf[2][B_SZ * H_SZ];

// ---------------- helpers ----------------
__device__ __forceinline__ float sigm(float x) {
    return 1.0f / (1.0f + __expf(-x));
}
__device__ __forceinline__ float tanh_(float x) {
    float e = __expf(-2.0f * fabsf(x));
    float r = (1.0f - e) / (1.0f + e);
    return copysignf(r, x);
}
__device__ __forceinline__ void cluster_sync() {
    asm volatile("barrier.cluster.arrive.aligned;" ::: "memory");
    asm volatile("barrier.cluster.wait.aligned;"   ::: "memory");
}

// ---------------- kernel ----------------
__global__ void __launch_bounds__(THREADS, 1) __cluster_dims__(CLC, 1, 1)
lstm_persistent_kernel(const float* __restrict__ x,
                       const float* __restrict__ Wf_h,  const float* __restrict__ Wf_x,  const float* __restrict__ bf,
                       const float* __restrict__ Wip_h, const float* __restrict__ Wip_x, const float* __restrict__ bip,
                       const float* __restrict__ Wit_h, const float* __restrict__ Wit_x, const float* __restrict__ bit_,
                       const float* __restrict__ Wo_h,  const float* __restrict__ Wo_x,  const float* __restrict__ bo,
                       float* __restrict__ out)
{
    extern __shared__ float smem[];
    float* As = smem;             // A_T[k][r]: k-major, stride 128, r = 4*h_local + gate
    float* Bs = smem + A_ELEMS;   // Bs[i][k]:  row-major, stride 388

    const int tid = threadIdx.x;
    const int c   = blockIdx.x & (CLC - 1);   // cluster rank = hidden-slice owner
    const int grp = blockIdx.x >> 3;          // batch group
    const int b0  = grp * NB;

    // ---- one-time weight staging: rows r = 0..127; thread pair handles one row.
    // row r -> (h_stage = r>>2, gate g = r&3); 256 threads, 2 threads per row split k.
    {
        const int r   = tid >> 1;             // 0..127
        const int khf = tid & 1;              // k half
        const int g   = r & 3;
        const int hs  = 32 * c + (r >> 2);
        const float* Wh = (g == 0) ? Wf_h : (g == 1) ? Wip_h : (g == 2) ? Wit_h : Wo_h;
        const float* Wx = (g == 0) ? Wf_x : (g == 1) ? Wip_x : (g == 2) ? Wit_x : Wo_x;
        #pragma unroll 4
        for (int k = khf * 128; k < khf * 128 + 128; k++)
            As[k * 128 + r] = Wh[k * H_SZ + hs];
        if (khf == 0) {
            #pragma unroll 4
            for (int k = 0; k < I_SZ; k++)
                As[(H_SZ + k) * 128 + r] = Wx[k * H_SZ + hs];
        }
    }

    // ---- compute mapping: h_local = tid & 31, batch pair p = tid >> 5 (0..7)
    const int h_local = tid & 31;
    const int p       = tid >> 5;             // batches 2p, 2p+1
    const int hg      = 32 * c + h_local;     // global hidden index

    const float bfv  = bf[hg];
    const float bipv = bip[hg];
    const float bitv = bit_[hg];
    const float bov  = bo[hg];

    // ---- zero step-0 read buffer (this thread's 2 epilogue cells)
    #pragma unroll
    for (int j = 0; j < 2; j++)
        __stcg(&g_shortbuf[0][(b0 + p * 2 + j) * H_SZ + hg], 0.0f);

    __syncthreads();
    cluster_sync();

    float longv[2] = {0.0f, 0.0f};

    const float* As_thr = As + 4 * h_local;           // + k*128 per k
    const float* Bs_thr = Bs + (p * 2) * B_STRIDE;

    #pragma unroll 1
    for (int t = 0; t < T_SZ; t++) {
        const int cur = t & 1;
        const int nxt = cur ^ 1;
        const float* sread = g_shortbuf[cur];

        // ===== stage B operand: Bs[i][0:256) = short, Bs[i][256:384) = x[b][t] =====
        #pragma unroll
        for (int it = 0; it < 6; it++) {
            int u  = tid + THREADS * it;      // 0..1535
            int i  = u / 96;                  // batch row 0..15
            int kq = u - i * 96;              // float4 index 0..95
            float4 v;
            if (kq < 64) {
                v = __ldcg((const float4*)(sread + (size_t)(b0 + i) * H_SZ + 4 * kq));
            } else {
                v = *(const float4*)(x + ((size_t)(b0 + i) * T_SZ + t) * I_SZ + 4 * (kq - 64));
            }
            *(float4*)(Bs + i * B_STRIDE + 4 * kq) = v;
        }
        __syncthreads();

        // ===== GEMM: acc[g][j] = sum_k A_T[k][4h+g] * Bs[2p+j][k] =====
        float acc[4][2];
        #pragma unroll
        for (int g = 0; g < 4; g++)
            #pragma unroll
            for (int j = 0; j < 2; j++)
                acc[g][j] = 0.0f;

        #pragma unroll 4
        for (int k = 0; k < KDIM; k += 4) {
            float4 a0 = *(const float4*)(As_thr + (k + 0) * 128);
            float4 a1 = *(const float4*)(As_thr + (k + 1) * 128);
            float4 a2 = *(const float4*)(As_thr + (k + 2) * 128);
            float4 a3 = *(const float4*)(As_thr + (k + 3) * 128);
            float4 bv[2];
            #pragma unroll
            for (int j = 0; j < 2; j++)
                bv[j] = *(const float4*)(Bs_thr + j * B_STRIDE + k);  // warp broadcast
            #pragma unroll
            for (int j = 0; j < 2; j++) {
                acc[0][j] += a0.x * bv[j].x; acc[1][j] += a0.y * bv[j].x;
                acc[2][j] += a0.z * bv[j].x; acc[3][j] += a0.w * bv[j].x;
                acc[0][j] += a1.x * bv[j].y; acc[1][j] += a1.y * bv[j].y;
                acc[2][j] += a1.z * bv[j].y; acc[3][j] += a1.w * bv[j].y;
                acc[0][j] += a2.x * bv[j].z; acc[1][j] += a2.y * bv[j].z;
                acc[2][j] += a2.z * bv[j].z; acc[3][j] += a2.w * bv[j].z;
                acc[0][j] += a3.x * bv[j].w; acc[1][j] += a3.y * bv[j].w;
                acc[2][j] += a3.z * bv[j].w; acc[3][j] += a3.w * bv[j].w;
            }
        }

        // ===== epilogue: gates, state update, publish new_short =====
        #pragma unroll
        for (int j = 0; j < 2; j++) {
            const int bb = b0 + p * 2 + j;
            float f  = sigm(acc[0][j] + bfv);
            float ip = sigm(acc[1][j] + bipv);
            float pt = tanh_(acc[2][j] + bitv);
            longv[j] = f * longv[j] + ip * pt;
            float o  = sigm(acc[3][j] + bov);
            float ns = tanh_(longv[j]) * o;
            __stcg(&g_shortbuf[nxt][bb * H_SZ + hg], ns);
            if (t == T_SZ - 1) {
                out[bb * H_SZ + hg]               = ns;        // short
                out[B_SZ * H_SZ + bb * H_SZ + hg] = longv[j];  // long
            }
        }

        // release new_short to cluster peers, acquire for next step's reads;
        // also serves as the block barrier protecting Bs reuse.
        cluster_sync();
    }
}

// ---------------- launch ----------------
extern "C" void kernel_launch(void* const* d_in, const int* in_sizes, int n_in,
                              void* d_out, int out_size)
{
    (void)in_sizes; (void)n_in; (void)out_size;
    const float* x     = (const float*)d_in[0];
    const float* Wf_h  = (const float*)d_in[1];
    const float* Wf_x  = (const float*)d_in[2];
    const float* bf    = (const float*)d_in[3];
    const float* Wip_h = (const float*)d_in[4];
    const float* Wip_x = (const float*)d_in[5];
    const float* bip   = (const float*)d_in[6];
    const float* Wit_h = (const float*)d_in[7];
    const float* Wit_x = (const float*)d_in[8];
    const float* bit_  = (const float*)d_in[9];
    const float* Wo_h  = (const float*)d_in[10];
    const float* Wo_x  = (const float*)d_in[11];
    const float* bo    = (const float*)d_in[12];
    float* out = (float*)d_out;

    cudaFuncSetAttribute(lstm_persistent_kernel,
                         cudaFuncAttributeMaxDynamicSharedMemorySize, SMEM_BYTES);

    lstm_persistent_kernel<<<GRID_CTAS, THREADS, SMEM_BYTES>>>(
        x, Wf_h, Wf_x, bf, Wip_h, Wip_x, bip,
        Wit_h, Wit_x, bit_, Wo_h, Wo_x, bo, out);
}

// round 5
// speedup vs baseline: 3.5085x; 3.5085x over previous
#include <cuda_runtime.h>
#include <cuda_bf16.h>
#include <cstdint>
#include <cstddef>

// ---------------- problem constants ----------------
#define B_SZ   256
#define T_SZ   1024
#define I_SZ   128
#define H_SZ   256
#define KD     384               // K = H + I (hi part); lo mirrored at +384
#define CLC    8                 // CTAs per cluster (hidden split)
#define NB     16                // batch rows per cluster
#define GRID_CTAS 128
#define THREADS 256              // 8 warps

// ---------------- SMEM layout ----------------
// A: [128 rows][SA] bf16, cols 0..383 = hi, 384..767 = lo; row r = 4*h_local + gate
// B: [16 rows][SB] bf16, cols 0..255 short-hi, 256..383 x-hi, 384..639 short-lo, 640..767 x-lo
#define SA 776                               // stride els: 1552B = 97*16B (odd -> conflict-free ldmatrix)
#define SB 776
#define A_ELEMS (128 * SA)                   // 99328 els = 198656 B
#define B_ELEMS (NB * SB)                    // 12416 els = 24832 B
#define SMEM_BYTES ((A_ELEMS + B_ELEMS) * 2) // 223488 B
#define SCR_STRIDE 18                        // fp32 scratch stride (reuses B region)

// packed (hi | lo<<16) bf16 short-state exchange, ping-pong, in L2
__device__ uint32_t g_short_pack[2][B_SZ * H_SZ];

// ---------------- helpers ----------------
__device__ __forceinline__ uint32_t smem_u32(const void* p) {
    uint32_t a;
    asm("{ .reg .u64 t; cvta.to.shared.u64 t, %1; cvt.u32.u64 %0, t; }" : "=r"(a) : "l"(p));
    return a;
}
__device__ __forceinline__ void cluster_sync() {
    asm volatile("barrier.cluster.arrive.aligned;" ::: "memory");
    asm volatile("barrier.cluster.wait.aligned;"   ::: "memory");
}
__device__ __forceinline__ void ldsm4(uint32_t* r, uint32_t addr) {
    asm volatile("ldmatrix.sync.aligned.m8n8.x4.shared.b16 {%0,%1,%2,%3}, [%4];"
                 : "=r"(r[0]), "=r"(r[1]), "=r"(r[2]), "=r"(r[3]) : "r"(addr));
}
__device__ __forceinline__ void mma16816(float* d, const uint32_t* a, const uint32_t* b) {
    asm volatile("mma.sync.aligned.m16n8k16.row.col.f32.bf16.bf16.f32 "
                 "{%0,%1,%2,%3}, {%4,%5,%6,%7}, {%8,%9}, {%0,%1,%2,%3};"
                 : "+f"(d[0]), "+f"(d[1]), "+f"(d[2]), "+f"(d[3])
                 : "r"(a[0]), "r"(a[1]), "r"(a[2]), "r"(a[3]), "r"(b[0]), "r"(b[1]));
}
__device__ __forceinline__ float sigm(float x) { return 1.0f / (1.0f + __expf(-x)); }
__device__ __forceinline__ float tanh_(float x) {
    float e = __expf(-2.0f * fabsf(x));
    return copysignf((1.0f - e) / (1.0f + e), x);
}

// ---------------- kernel ----------------
__global__ void __launch_bounds__(THREADS, 1) __cluster_dims__(CLC, 1, 1)
lstm_mma_kernel(const float* __restrict__ x,
                const float* __restrict__ Wf_h,  const float* __restrict__ Wf_x,  const float* __restrict__ bf,
                const float* __restrict__ Wip_h, const float* __restrict__ Wip_x, const float* __restrict__ bip,
                const float* __restrict__ Wit_h, const float* __restrict__ Wit_x, const float* __restrict__ bit_,
                const float* __restrict__ Wo_h,  const float* __restrict__ Wo_x,  const float* __restrict__ bo,
                float* __restrict__ out)
{
    extern __shared__ __nv_bfloat16 smem[];
    __nv_bfloat16* As = smem;
    __nv_bfloat16* Bs = smem + A_ELEMS;
    float* scr = (float*)Bs;                 // epilogue scratch aliases B region

    const uint32_t sbA = smem_u32(As);
    const uint32_t sbB = smem_u32(Bs);

    const int tid = threadIdx.x;
    const int w   = tid >> 5;
    const int l   = tid & 31;
    const int c   = blockIdx.x & (CLC - 1);  // hidden-slice owner within cluster
    const int grp = blockIdx.x >> 3;
    const int b0  = grp * NB;

    // ---- one-time weight staging: row r = 4*h_local + gate ----
    {
        const int r  = tid >> 1;             // 0..127
        const int kh = tid & 1;              // k half (192 each)
        const int g  = r & 3;
        const int hs = 32 * c + (r >> 2);
        const float* Wh = (g == 0) ? Wf_h : (g == 1) ? Wip_h : (g == 2) ? Wit_h : Wo_h;
        const float* Wx = (g == 0) ? Wf_x : (g == 1) ? Wip_x : (g == 2) ? Wit_x : Wo_x;
        #pragma unroll 4
        for (int k = kh * 192; k < kh * 192 + 192; k++) {
            float v = (k < H_SZ) ? Wh[(size_t)k * H_SZ + hs] : Wx[(size_t)(k - H_SZ) * H_SZ + hs];
            __nv_bfloat16 hi = __float2bfloat16_rn(v);
            __nv_bfloat16 lo = __float2bfloat16_rn(v - __bfloat162float(hi));
            As[r * SA + k]       = hi;
            As[r * SA + KD + k]  = lo;
        }
    }

    // ---- ldmatrix lane base addresses (bytes) ----
    // A x4 blocks: lanes 0-7 -> A[16w+i][k], 8-15 -> A[16w+8+i][k], 16-23 -> A[16w+i][k+8], 24-31 -> A[16w+8+i][k+8]
    const uint32_t a_lane = sbA + (uint32_t)(((16 * w + (l & 7) + 8 * ((l >> 3) & 1)) * SA + 8 * (l >> 4)) * 2);
    // B x4 blocks: lanes 0-7 -> B[i][k], 8-15 -> B[i][k+8], 16-23 -> B[8+i][k], 24-31 -> B[8+i][k+8]
    const uint32_t b_lane = sbB + (uint32_t)((((l & 7) + 8 * (l >> 4)) * SB + 8 * ((l >> 3) & 1)) * 2);

    // ---- epilogue mapping (persistent) ----
    const int hl  = tid >> 3;                // hidden 0..31
    const int bq  = (tid & 7) * 2;           // batch pair base
    const int hg  = 32 * c + hl;
    const float bfv  = bf[hg];
    const float bipv = bip[hg];
    const float bitv = bit_[hg];
    const float bov  = bo[hg];
    float longv[2] = {0.0f, 0.0f};

    // ---- zero step-0 short buffer (own slice: 16 rows x 32 cols) ----
    {
        int i  = tid >> 4;
        int cc = 32 * c + (tid & 15) * 2;
        g_short_pack[0][(b0 + i) * H_SZ + cc]     = 0u;
        g_short_pack[0][(b0 + i) * H_SZ + cc + 1] = 0u;
    }

    // ---- x prefetch mapping: thread -> (row xi, 8 contiguous x cols at kx0) ----
    const int xi  = tid >> 4;
    const int kx0 = (tid & 15) * 8;
    const float* xrow = x + (size_t)(b0 + xi) * T_SZ * I_SZ + kx0;
    float4 xr0 = *(const float4*)(xrow + 0);
    float4 xr1 = *(const float4*)(xrow + 4);

    __syncthreads();
    cluster_sync();

    #pragma unroll 1
    for (int t = 0; t < T_SZ; t++) {
        const int cur = t & 1;
        const int nxt = cur ^ 1;

        // ===== stage B tile =====
        {
            const uint32_t* srow = g_short_pack[cur] + (size_t)(b0 + xi) * H_SZ;
            __nv_bfloat16* brow = Bs + xi * SB;
            #pragma unroll
            for (int n = 0; n < 4; n++) {
                int hb = ((tid & 15) * 4 + n) * 4;     // h base, 4 cols per uint4
                uint4 v = __ldcg((const uint4*)(srow + hb));
                uint32_t hi01 = __byte_perm(v.x, v.y, 0x5410);
                uint32_t lo01 = __byte_perm(v.x, v.y, 0x7632);
                uint32_t hi23 = __byte_perm(v.z, v.w, 0x5410);
                uint32_t lo23 = __byte_perm(v.z, v.w, 0x7632);
                *(uint32_t*)&brow[hb]            = hi01;
                *(uint32_t*)&brow[hb + 2]        = hi23;
                *(uint32_t*)&brow[KD + hb]       = lo01;
                *(uint32_t*)&brow[KD + hb + 2]   = lo23;
            }
            // x part from prefetch regs -> hi at 256+kx, lo at 640+kx
            float xf[8] = {xr0.x, xr0.y, xr0.z, xr0.w, xr1.x, xr1.y, xr1.z, xr1.w};
            #pragma unroll
            for (int m = 0; m < 4; m++) {
                float f0 = xf[2 * m], f1 = xf[2 * m + 1];
                __nv_bfloat16 h0 = __float2bfloat16_rn(f0);
                __nv_bfloat16 h1 = __float2bfloat16_rn(f1);
                __nv_bfloat16 l0 = __float2bfloat16_rn(f0 - __bfloat162float(h0));
                __nv_bfloat16 l1 = __float2bfloat16_rn(f1 - __bfloat162float(h1));
                uint32_t hp = (uint32_t)__bfloat16_as_ushort(h0) | ((uint32_t)__bfloat16_as_ushort(h1) << 16);
                uint32_t lp = (uint32_t)__bfloat16_as_ushort(l0) | ((uint32_t)__bfloat16_as_ushort(l1) << 16);
                *(uint32_t*)&brow[256 + kx0 + 2 * m] = hp;
                *(uint32_t*)&brow[640 + kx0 + 2 * m] = lp;
            }
        }
        __syncthreads();

        // prefetch x(t+1) (overlaps the mma block)
        {
            int tn = (t + 1 < T_SZ) ? t + 1 : t;
            xr0 = *(const float4*)(xrow + (size_t)tn * I_SZ + 0);
            xr1 = *(const float4*)(xrow + (size_t)tn * I_SZ + 4);
        }

        // ===== GEMM: 3-term bf16 split, fp32 accum in registers =====
        float acc0[4] = {0.f, 0.f, 0.f, 0.f};     // ntile 0 (batch 0-7)
        float acc1[4] = {0.f, 0.f, 0.f, 0.f};     // ntile 1 (batch 8-15)
        #pragma unroll 4
        for (int kc = 0; kc < 24; kc++) {
            const uint32_t kb = (uint32_t)kc * 32; // 16 els * 2B
            uint32_t ah[4], al[4], bh[4], bl[4];
            ldsm4(ah, a_lane + kb);
            ldsm4(al, a_lane + 768 + kb);          // A lo (+384 els)
            ldsm4(bh, b_lane + kb);
            ldsm4(bl, b_lane + 768 + kb);          // B lo
            mma16816(acc0, ah, bh + 0);
            mma16816(acc1, ah, bh + 2);
            mma16816(acc0, al, bh + 0);
            mma16816(acc1, al, bh + 2);
            mma16816(acc0, ah, bl + 0);
            mma16816(acc1, ah, bl + 2);
        }
        __syncthreads();   // all warps done reading Bs before scr overwrite

        // ===== store accum frags to scratch (transpose for epilogue) =====
        {
            const int r0 = 16 * w + (l >> 2);
            const int c0 = (l & 3) * 2;
            *(float2*)&scr[r0 * SCR_STRIDE + c0]           = make_float2(acc0[0], acc0[1]);
            *(float2*)&scr[(r0 + 8) * SCR_STRIDE + c0]     = make_float2(acc0[2], acc0[3]);
            *(float2*)&scr[r0 * SCR_STRIDE + 8 + c0]       = make_float2(acc1[0], acc1[1]);
            *(float2*)&scr[(r0 + 8) * SCR_STRIDE + 8 + c0] = make_float2(acc1[2], acc1[3]);
        }
        __syncthreads();

        // ===== epilogue: 2 cells (hl, bq), (hl, bq+1) =====
        {
            float2 zf = *(float2*)&scr[(4 * hl + 0) * SCR_STRIDE + bq];
            float2 zi = *(float2*)&scr[(4 * hl + 1) * SCR_STRIDE + bq];
            float2 zp = *(float2*)&scr[(4 * hl + 2) * SCR_STRIDE + bq];
            float2 zo = *(float2*)&scr[(4 * hl + 3) * SCR_STRIDE + bq];
            float zfv[2] = {zf.x, zf.y}, ziv[2] = {zi.x, zi.y};
            float zpv[2] = {zp.x, zp.y}, zov[2] = {zo.x, zo.y};
            #pragma unroll
            for (int j = 0; j < 2; j++) {
                const int bb = b0 + bq + j;
                float f  = sigm(zfv[j] + bfv);
                float ip = sigm(ziv[j] + bipv);
                float pt = tanh_(zpv[j] + bitv);
                longv[j] = f * longv[j] + ip * pt;
                float o  = sigm(zov[j] + bov);
                float ns = tanh_(longv[j]) * o;
                __nv_bfloat16 hi = __float2bfloat16_rn(ns);
                __nv_bfloat16 lo = __float2bfloat16_rn(ns - __bfloat162float(hi));
                uint32_t pk = (uint32_t)__bfloat16_as_ushort(hi) | ((uint32_t)__bfloat16_as_ushort(lo) << 16);
                __stcg(&g_short_pack[nxt][(size_t)bb * H_SZ + hg], pk);
                if (t == T_SZ - 1) {
                    out[(size_t)bb * H_SZ + hg]                       = ns;        // short
                    out[(size_t)B_SZ * H_SZ + (size_t)bb * H_SZ + hg] = longv[j];  // long
                }
            }
        }

        cluster_sync();  // publish short state; guards Bs/scr reuse next step
    }
}

// ---------------- launch ----------------
extern "C" void kernel_launch(void* const* d_in, const int* in_sizes, int n_in,
                              void* d_out, int out_size)
{
    (void)in_sizes; (void)n_in; (void)out_size;
    const float* x     = (const float*)d_in[0];
    const float* Wf_h  = (const float*)d_in[1];
    const float* Wf_x  = (const float*)d_in[2];
    const float* bf    = (const float*)d_in[3];
    const float* Wip_h = (const float*)d_in[4];
    const float* Wip_x = (const float*)d_in[5];
    const float* bip   = (const float*)d_in[6];
    const float* Wit_h = (const float*)d_in[7];
    const float* Wit_x = (const float*)d_in[8];
    const float* bit_  = (const float*)d_in[9];
    const float* Wo_h  = (const float*)d_in[10];
    const float* Wo_x  = (const float*)d_in[11];
    const float* bo    = (const float*)d_in[12];
    float* out = (float*)d_out;

    cudaFuncSetAttribute(lstm_mma_kernel,
                         cudaFuncAttributeMaxDynamicSharedMemorySize, SMEM_BYTES);

    lstm_mma_kernel<<<GRID_CTAS, THREADS, SMEM_BYTES>>>(
        x, Wf_h, Wf_x, bf, Wip_h, Wip_x, bip,
        Wit_h, Wit_x, bit_, Wo_h, Wo_x, bo, out);
}